// round 7
// baseline (speedup 1.0000x reference)
#include <cuda_runtime.h>
#include <cuda_fp16.h>
#include <math.h>
#include <stdint.h>

#define N_TOK 4096
#define D_MOD 512

// scratch (static device globals — no allocation allowed)
__device__ __half g_Xh[N_TOK * D_MOD];
__device__ __half g_Wqh[D_MOD * D_MOD];
__device__ __half g_Wkh[D_MOD * D_MOD];
__device__ __half g_Wvh[D_MOD * D_MOD];
__device__ __half g_Qh[N_TOK * D_MOD];
__device__ __half g_Kh[N_TOK * D_MOD];
__device__ __half g_Vh[N_TOK * D_MOD];
__device__ __half g_Vth[D_MOD * N_TOK];      // V^T [512][4096]
__device__ __half g_Sh[(size_t)N_TOK * N_TOK];
__device__ float  g_sigma[N_TOK];

__device__ __forceinline__ uint32_t smem_u32(const void* p) {
    uint32_t a;
    asm("{ .reg .u64 t; cvta.to.shared.u64 t, %1; cvt.u32.u64 %0, t; }" : "=r"(a) : "l"(p));
    return a;
}
__device__ __forceinline__ void mma_f16(float* d, const uint32_t* a, const uint32_t* b) {
    asm volatile(
        "mma.sync.aligned.m16n8k16.row.col.f32.f16.f16.f32 "
        "{%0,%1,%2,%3}, {%4,%5,%6,%7}, {%8,%9}, {%0,%1,%2,%3};"
        : "+f"(d[0]), "+f"(d[1]), "+f"(d[2]), "+f"(d[3])
        : "r"(a[0]), "r"(a[1]), "r"(a[2]), "r"(a[3]), "r"(b[0]), "r"(b[1]));
}
__device__ __forceinline__ void ldsm4(uint32_t* r, uint32_t addr) {
    asm volatile("ldmatrix.sync.aligned.m8n8.x4.shared.b16 {%0,%1,%2,%3}, [%4];"
        : "=r"(r[0]), "=r"(r[1]), "=r"(r[2]), "=r"(r[3]) : "r"(addr));
}
__device__ __forceinline__ void cp16(uint32_t s, const void* g) {
    asm volatile("cp.async.cg.shared.global [%0], [%1], 16;" :: "r"(s), "l"(g));
}

// ---------------------------------------------------------------------------
// cp.async 4-stage fp16 GEMM (fp32 accumulate), ldmatrix fragment loads.
//   C[M,NC] = alpha * A[M,K] * B[NC,K]^T   (both K-major row-major fp16)
// XOR-swizzled chunk layout; BM=BN=128, BK=64, 256 threads, warp tile 64x32.
// row_base: global row offset (for row-half pipelining).
// ---------------------------------------------------------------------------
#define STAGES 4
#define TILE_BYTES 16384
#define STAGE_BYTES (2 * TILE_BYTES)
#define DYN_SMEM (STAGES * STAGE_BYTES)       // 128 KB

template <bool OUT_HALF>
__device__ __forceinline__ void gemm_fp16(
    const __half* __restrict__ A, const __half* __restrict__ B,
    void* __restrict__ Cv, int K, int NC, float alpha, int row_base)
{
    extern __shared__ __half smh[];
    const uint32_t smem_base = smem_u32(smh);
    const int t    = threadIdx.x;
    const int wid  = t >> 5;
    const int lane = t & 31;
    const int r    = lane >> 2;
    const int c    = lane & 3;
    const int warpM = (wid >> 2) * 64;
    const int warpN = (wid & 3) * 32;
    const int row0 = row_base + blockIdx.y * 128;
    const int col0 = blockIdx.x * 128;
    const int iters = K >> 6;

    auto stage_load = [&](int sidx) {
        const int buf = sidx & (STAGES - 1);
        const int k0  = sidx << 6;
        const uint32_t abase = smem_base + (uint32_t)buf * STAGE_BYTES;
        const uint32_t bbase = abase + TILE_BYTES;
#pragma unroll
        for (int i = 0; i < 4; i++) {
            int lc = i * 256 + t;
            int rr = lc >> 3, cc = lc & 7;
            uint32_t so = (uint32_t)((rr << 3) + (cc ^ (rr & 7))) << 4;
            cp16(abase + so, &A[(size_t)(row0 + rr) * K + k0 + (cc << 3)]);
            cp16(bbase + so, &B[(size_t)(col0 + rr) * K + k0 + (cc << 3)]);
        }
        asm volatile("cp.async.commit_group;" ::: "memory");
    };

    const int a_row_lo = lane & 15;
    const int a_chi    = lane >> 4;
    const int b_row_lo = (lane & 7) + ((lane >> 4) << 3);
    const int b_chi    = (lane >> 3) & 1;

    float acc[4][4][4] = {};

    stage_load(0);
    stage_load(1);
    stage_load(2);

    for (int it = 0; it < iters; ++it) {
        const int buf = it & (STAGES - 1);
        asm volatile("cp.async.wait_group %0;" :: "n"(STAGES - 2) : "memory");
        __syncthreads();
        if (it + STAGES - 1 < iters) stage_load(it + STAGES - 1);

        const uint32_t abase = smem_base + (uint32_t)buf * STAGE_BYTES;
        const uint32_t bbase = abase + TILE_BYTES;

#pragma unroll
        for (int kk4 = 0; kk4 < 4; kk4++) {
            const int ca = kk4 * 2 + a_chi;
            const int cb = kk4 * 2 + b_chi;
            uint32_t af[4][4], bq[2][4];
#pragma unroll
            for (int mi = 0; mi < 4; mi++) {
                int row = warpM + mi * 16 + a_row_lo;
                uint32_t addr = abase + ((uint32_t)((row << 3) + (ca ^ (row & 7))) << 4);
                ldsm4(af[mi], addr);
            }
#pragma unroll
            for (int np = 0; np < 2; np++) {
                int row = warpN + np * 16 + b_row_lo;
                uint32_t addr = bbase + ((uint32_t)((row << 3) + (cb ^ (row & 7))) << 4);
                ldsm4(bq[np], addr);
            }
#pragma unroll
            for (int mi = 0; mi < 4; mi++)
#pragma unroll
                for (int ni = 0; ni < 4; ni++)
                    mma_f16(acc[mi][ni], af[mi], &bq[ni >> 1][(ni & 1) * 2]);
        }
    }

#pragma unroll
    for (int mi = 0; mi < 4; mi++) {
        int row = row0 + warpM + mi * 16 + r;
#pragma unroll
        for (int ni = 0; ni < 4; ni++) {
            int col = col0 + warpN + ni * 8 + 2 * c;
            float o0 = alpha * acc[mi][ni][0], o1 = alpha * acc[mi][ni][1];
            float o2 = alpha * acc[mi][ni][2], o3 = alpha * acc[mi][ni][3];
            if (OUT_HALF) {
                __half* Ch = (__half*)Cv;
                *(__half2*)&Ch[(size_t)row * NC + col]       = __floats2half2_rn(o0, o1);
                *(__half2*)&Ch[(size_t)(row + 8) * NC + col] = __floats2half2_rn(o2, o3);
            } else {
                float* Cf = (float*)Cv;
                *(float2*)&Cf[(size_t)row * NC + col]       = make_float2(o0, o1);
                *(float2*)&Cf[(size_t)(row + 8) * NC + col] = make_float2(o2, o3);
            }
        }
    }
}

__global__ void __launch_bounds__(256) qkv_h_kernel()
{
    if (blockIdx.z == 0)      gemm_fp16<true>(g_Xh, g_Wqh, g_Qh, D_MOD, D_MOD, 1.0f, 0);
    else if (blockIdx.z == 1) gemm_fp16<true>(g_Xh, g_Wkh, g_Kh, D_MOD, D_MOD, 1.0f, 0);
    else                      gemm_fp16<true>(g_Xh, g_Wvh, g_Vh, D_MOD, D_MOD, 1.0f, 0);
}

__global__ void __launch_bounds__(256) s_h_kernel(float* __restrict__ S, int row_base)
{
    gemm_fp16<false>(g_Qh, g_Kh, S, D_MOD, N_TOK, 0.044194173824159216f, row_base);
}

__global__ void __launch_bounds__(256) z_h_kernel(float* __restrict__ Z, int row_base)
{
    gemm_fp16<false>(g_Sh, g_Vth, Z, N_TOK, D_MOD, 1.0f, row_base);
}

// ---------------------------------------------------------------------------
// fused fp32 -> fp16 convert for x, Wq, Wk, Wv (one launch)
// ---------------------------------------------------------------------------
#define X4   (N_TOK * D_MOD / 4)
#define W4   (D_MOD * D_MOD / 4)

__global__ void cvt_all_kernel(const float4* __restrict__ x,
                               const float4* __restrict__ Wq,
                               const float4* __restrict__ Wk,
                               const float4* __restrict__ Wv)
{
    int i = blockIdx.x * blockDim.x + threadIdx.x;
    const float4* in;
    __half* out;
    int idx;
    if (i < X4)                { in = x;  out = g_Xh;  idx = i; }
    else if (i < X4 + W4)      { in = Wq; out = g_Wqh; idx = i - X4; }
    else if (i < X4 + 2 * W4)  { in = Wk; out = g_Wkh; idx = i - X4 - W4; }
    else if (i < X4 + 3 * W4)  { in = Wv; out = g_Wvh; idx = i - X4 - 2 * W4; }
    else return;
    float4 v = in[idx];
    *(__half2*)&out[idx * 4]     = __floats2half2_rn(v.x, v.y);
    *(__half2*)&out[idx * 4 + 2] = __floats2half2_rn(v.z, v.w);
}

// ---------------------------------------------------------------------------
// transpose g_Vh [4096][512] -> g_Vth [512][4096]
// ---------------------------------------------------------------------------
__global__ void transpose_v_kernel()
{
    __shared__ __half tile[32][33];
    const int c0 = blockIdx.x * 32;
    const int r0 = blockIdx.y * 32;
    const int tx = threadIdx.x & 31;
    const int ty = threadIdx.x >> 5;
#pragma unroll
    for (int i = 0; i < 4; i++) {
        int row = ty + i * 8;
        tile[row][tx] = g_Vh[(size_t)(r0 + row) * D_MOD + c0 + tx];
    }
    __syncthreads();
#pragma unroll
    for (int i = 0; i < 4; i++) {
        int row = ty + i * 8;
        g_Vth[(size_t)(c0 + row) * N_TOK + r0 + tx] = tile[tx][row];
    }
}

// ---------------------------------------------------------------------------
// sigma[i] = clip(x[i,:].Ws, 0.001, 1.0) — one warp per row (fp32 inputs)
// ---------------------------------------------------------------------------
__global__ void sigma_kernel(const float* __restrict__ x, const float* __restrict__ Ws)
{
    int row  = blockIdx.x * (blockDim.x >> 5) + (threadIdx.x >> 5);
    int lane = threadIdx.x & 31;
    if (row >= N_TOK) return;
    const float4* xr = (const float4*)(x + (size_t)row * D_MOD);
    const float4* w  = (const float4*)Ws;
    float s = 0.f;
#pragma unroll
    for (int k = lane; k < D_MOD / 4; k += 32) {
        float4 a = xr[k], b = w[k];
        s += a.x * b.x + a.y * b.y + a.z * b.z + a.w * b.w;
    }
#pragma unroll
    for (int o = 16; o; o >>= 1) s += __shfl_xor_sync(0xffffffffu, s, o);
    if (lane == 0) g_sigma[row] = fminf(fmaxf(s, 0.001f), 1.0f);
}

// ---------------------------------------------------------------------------
// P row kernel: zero the row, then Gaussian band (fp32 underflow makes the
// exp term exactly 0 for |i-j| >= 15 since sigma <= 1). One block per row.
// ---------------------------------------------------------------------------
#define BAND 32

__global__ void p_row_kernel(float* __restrict__ P)
{
    const int row = blockIdx.x;
    const int t = threadIdx.x;
    float4* prow4 = (float4*)(P + (size_t)row * N_TOK);
#pragma unroll
    for (int j = t; j < N_TOK / 4; j += 256)
        prow4[j] = make_float4(0.f, 0.f, 0.f, 0.f);
    __syncthreads();

    if (t < 32) {
        const int lane = t;
        const float sg  = g_sigma[row];
        const float inv = 1.0f / sg;
        const float cc  = rsqrtf(6.283185307179586f * sg);
        const int j0 = max(row - BAND, 0);
        const int j1 = min(row + BAND, N_TOK - 1);

        float sum = 0.f;
        for (int j = j0 + lane; j <= j1; j += 32) {
            float u = (float)(j - row) * inv;
            sum += cc * __expf(-0.5f * u * u);
        }
#pragma unroll
        for (int o = 16; o; o >>= 1) sum += __shfl_xor_sync(0xffffffffu, sum, o);
        const float scale = 1.0f / (sum + 1e-8f);

        for (int j = j0 + lane; j <= j1; j += 32) {
            float u = (float)(j - row) * inv;
            P[(size_t)row * N_TOK + j] = cc * __expf(-0.5f * u * u) * scale;
        }
    }
}

// ---------------------------------------------------------------------------
// in-place row softmax (no max pass: scores ~N(0,1), far from fp32 overflow),
// also writes fp16 copy. One block per row; row_base for half-pipelining.
// ---------------------------------------------------------------------------
__global__ void softmax_kernel(float* __restrict__ S, __half* __restrict__ Sh,
                               int row_base)
{
    __shared__ float buf[N_TOK];
    __shared__ float red[8];
    const int row = row_base + blockIdx.x;
    const int t = threadIdx.x;
    const int lane = t & 31, w = t >> 5;
    float*  srow  = S  + (size_t)row * N_TOK;
    __half* srowh = Sh + (size_t)row * N_TOK;

    float sum = 0.f;
    for (int j = t; j < N_TOK; j += 256) {
        float e = __expf(srow[j]);
        buf[j] = e;
        sum += e;
    }
#pragma unroll
    for (int o = 16; o; o >>= 1) sum += __shfl_xor_sync(0xffffffffu, sum, o);
    if (lane == 0) red[w] = sum;
    __syncthreads();
    if (t == 0) {
        float s = 0.f;
#pragma unroll
        for (int i = 0; i < 8; i++) s += red[i];
        red[0] = s;
    }
    __syncthreads();
    const float scale = 1.0f / red[0];

    for (int j = t; j < N_TOK; j += 256) {
        float v = buf[j] * scale;
        srow[j]  = v;
        srowh[j] = __float2half_rn(v);
    }
}

// ---------------------------------------------------------------------------
extern "C" void kernel_launch(void* const* d_in, const int* in_sizes, int n_in,
                              void* d_out, int out_size)
{
    const float* x  = (const float*)d_in[0];
    const float* Wq = (const float*)d_in[1];
    const float* Wk = (const float*)d_in[2];
    const float* Wv = (const float*)d_in[3];
    const float* Ws = (const float*)d_in[4];

    float* out = (float*)d_out;
    float* Z = out;                          // [4096, 512]
    float* P = out + (size_t)N_TOK * D_MOD;  // [4096, 4096]
    float* S = P + (size_t)N_TOK * N_TOK;    // [4096, 4096]

    static cudaStream_t sA = nullptr, sB = nullptr;
    static cudaEvent_t eQKV, eS0, eS1, eSM0, eSM1, eT, eFork;
    if (!sA) {
        cudaStreamCreateWithFlags(&sA, cudaStreamNonBlocking);
        cudaStreamCreateWithFlags(&sB, cudaStreamNonBlocking);
        cudaEventCreateWithFlags(&eQKV, cudaEventDisableTiming);
        cudaEventCreateWithFlags(&eS0,  cudaEventDisableTiming);
        cudaEventCreateWithFlags(&eS1,  cudaEventDisableTiming);
        cudaEventCreateWithFlags(&eSM0, cudaEventDisableTiming);
        cudaEventCreateWithFlags(&eSM1, cudaEventDisableTiming);
        cudaEventCreateWithFlags(&eT,   cudaEventDisableTiming);
        cudaEventCreateWithFlags(&eFork, cudaEventDisableTiming);

        cudaFuncSetAttribute(qkv_h_kernel, cudaFuncAttributeMaxDynamicSharedMemorySize, DYN_SMEM);
        cudaFuncSetAttribute(s_h_kernel,   cudaFuncAttributeMaxDynamicSharedMemorySize, DYN_SMEM);
        cudaFuncSetAttribute(z_h_kernel,   cudaFuncAttributeMaxDynamicSharedMemorySize, DYN_SMEM);
    }

    __half* shp;
    cudaGetSymbolAddress((void**)&shp, g_Sh);

    dim3 blk(256);
    const int HALF = N_TOK / 2;   // 2048 rows

    // fork point: sA handles sigma -> p_row (independent of GEMM chain)
    cudaEventRecord(eFork, 0);
    cudaStreamWaitEvent(sA, eFork, 0);
    sigma_kernel<<<N_TOK / 8, blk, 0, sA>>>(x, Ws);
    p_row_kernel<<<N_TOK, blk, 0, sA>>>(P);

    // main chain: cvt -> qkv
    cvt_all_kernel<<<(X4 + 3 * W4 + 255) / 256, blk>>>(
        (const float4*)x, (const float4*)Wq, (const float4*)Wk, (const float4*)Wv);
    dim3 gQKV(D_MOD / 128, N_TOK / 128, 3);
    qkv_h_kernel<<<gQKV, blk, DYN_SMEM>>>();
    cudaEventRecord(eQKV, 0);

    // sB: transpose V (needs qkv)
    cudaStreamWaitEvent(sB, eQKV, 0);
    transpose_v_kernel<<<dim3(D_MOD / 32, N_TOK / 32), blk, 0, sB>>>();
    cudaEventRecord(eT, sB);

    // S GEMM halves on main stream
    dim3 gSh(N_TOK / 128, HALF / 128);
    s_h_kernel<<<gSh, blk, DYN_SMEM>>>(S, 0);
    cudaEventRecord(eS0, 0);
    s_h_kernel<<<gSh, blk, DYN_SMEM>>>(S, HALF);
    cudaEventRecord(eS1, 0);

    // softmax halves on sA (after p_row in stream order)
    cudaStreamWaitEvent(sA, eS0, 0);
    softmax_kernel<<<HALF, blk, 0, sA>>>(S, shp, 0);
    cudaEventRecord(eSM0, sA);
    cudaStreamWaitEvent(sA, eS1, 0);
    softmax_kernel<<<HALF, blk, 0, sA>>>(S, shp, HALF);
    cudaEventRecord(eSM1, sA);

    // Z GEMM halves on main stream, overlapping softmax of the other half
    dim3 gZh(D_MOD / 128, HALF / 128);
    cudaStreamWaitEvent(0, eSM0, 0);
    cudaStreamWaitEvent(0, eT, 0);
    z_h_kernel<<<gZh, blk, DYN_SMEM>>>(Z, 0);
    cudaStreamWaitEvent(0, eSM1, 0);
    z_h_kernel<<<gZh, blk, DYN_SMEM>>>(Z, HALF);
}

// round 8
// speedup vs baseline: 1.3546x; 1.3546x over previous
#include <cuda_runtime.h>
#include <cuda_fp16.h>
#include <math.h>
#include <stdint.h>

#define N_TOK 4096
#define D_MOD 512

// scratch (static device globals — no allocation allowed)
__device__ __half g_Xh[N_TOK * D_MOD];
__device__ __half g_Wqh[D_MOD * D_MOD];
__device__ __half g_Wkh[D_MOD * D_MOD];
__device__ __half g_Wvh[D_MOD * D_MOD];
__device__ __half g_Qh[N_TOK * D_MOD];
__device__ __half g_Kh[N_TOK * D_MOD];
__device__ __half g_Vh[N_TOK * D_MOD];
__device__ __half g_Vth[D_MOD * N_TOK];      // V^T [512][4096]
__device__ __half g_Sh[(size_t)N_TOK * N_TOK];
__device__ float  g_sigma[N_TOK];

__device__ __forceinline__ uint32_t smem_u32(const void* p) {
    uint32_t a;
    asm("{ .reg .u64 t; cvta.to.shared.u64 t, %1; cvt.u32.u64 %0, t; }" : "=r"(a) : "l"(p));
    return a;
}
__device__ __forceinline__ void mma_f16(float* d, const uint32_t* a, const uint32_t* b) {
    asm volatile(
        "mma.sync.aligned.m16n8k16.row.col.f32.f16.f16.f32 "
        "{%0,%1,%2,%3}, {%4,%5,%6,%7}, {%8,%9}, {%0,%1,%2,%3};"
        : "+f"(d[0]), "+f"(d[1]), "+f"(d[2]), "+f"(d[3])
        : "r"(a[0]), "r"(a[1]), "r"(a[2]), "r"(a[3]), "r"(b[0]), "r"(b[1]));
}
__device__ __forceinline__ void ldsm4(uint32_t* r, uint32_t addr) {
    asm volatile("ldmatrix.sync.aligned.m8n8.x4.shared.b16 {%0,%1,%2,%3}, [%4];"
        : "=r"(r[0]), "=r"(r[1]), "=r"(r[2]), "=r"(r[3]) : "r"(addr));
}
__device__ __forceinline__ void cp16(uint32_t s, const void* g) {
    asm volatile("cp.async.cg.shared.global [%0], [%1], 16;" :: "r"(s), "l"(g));
}

// ---------------------------------------------------------------------------
// cp.async 3-stage fp16 GEMM (fp32 accumulate), ldmatrix fragment loads.
//   C[M,NC] = alpha * A[M,K] * B[NC,K]^T   (both K-major row-major fp16)
// XOR-swizzled chunk layout; BM=BN=128, BK=64, 256 threads, warp tile 64x32.
// 96 KB smem -> 2 CTAs/SM (16 warps) for tensor-pipe latency hiding.
// ---------------------------------------------------------------------------
#define STAGES 3
#define TILE_BYTES 16384
#define STAGE_BYTES (2 * TILE_BYTES)
#define DYN_SMEM (STAGES * STAGE_BYTES)       // 96 KB

template <bool OUT_HALF>
__device__ __forceinline__ void gemm_fp16(
    const __half* __restrict__ A, const __half* __restrict__ B,
    void* __restrict__ Cv, int K, int NC, float alpha)
{
    extern __shared__ __half smh[];
    const uint32_t smem_base = smem_u32(smh);
    const int t    = threadIdx.x;
    const int wid  = t >> 5;
    const int lane = t & 31;
    const int r    = lane >> 2;
    const int c    = lane & 3;
    const int warpM = (wid >> 2) * 64;
    const int warpN = (wid & 3) * 32;
    const int row0 = blockIdx.y * 128;
    const int col0 = blockIdx.x * 128;
    const int iters = K >> 6;

    auto stage_load = [&](int sidx) {
        const int buf = sidx % STAGES;
        const int k0  = sidx << 6;
        const uint32_t abase = smem_base + (uint32_t)buf * STAGE_BYTES;
        const uint32_t bbase = abase + TILE_BYTES;
#pragma unroll
        for (int i = 0; i < 4; i++) {
            int lc = i * 256 + t;
            int rr = lc >> 3, cc = lc & 7;
            uint32_t so = (uint32_t)((rr << 3) + (cc ^ (rr & 7))) << 4;
            cp16(abase + so, &A[(size_t)(row0 + rr) * K + k0 + (cc << 3)]);
            cp16(bbase + so, &B[(size_t)(col0 + rr) * K + k0 + (cc << 3)]);
        }
        asm volatile("cp.async.commit_group;" ::: "memory");
    };

    const int a_row_lo = lane & 15;
    const int a_chi    = lane >> 4;
    const int b_row_lo = (lane & 7) + ((lane >> 4) << 3);
    const int b_chi    = (lane >> 3) & 1;

    float acc[4][4][4] = {};

    stage_load(0);
    stage_load(1);

    for (int it = 0; it < iters; ++it) {
        const int buf = it % STAGES;
        asm volatile("cp.async.wait_group %0;" :: "n"(STAGES - 2) : "memory");
        __syncthreads();
        if (it + STAGES - 1 < iters) stage_load(it + STAGES - 1);

        const uint32_t abase = smem_base + (uint32_t)buf * STAGE_BYTES;
        const uint32_t bbase = abase + TILE_BYTES;

#pragma unroll
        for (int kk4 = 0; kk4 < 4; kk4++) {
            const int ca = kk4 * 2 + a_chi;
            const int cb = kk4 * 2 + b_chi;
            uint32_t af[4][4], bq[2][4];
#pragma unroll
            for (int mi = 0; mi < 4; mi++) {
                int row = warpM + mi * 16 + a_row_lo;
                uint32_t addr = abase + ((uint32_t)((row << 3) + (ca ^ (row & 7))) << 4);
                ldsm4(af[mi], addr);
            }
#pragma unroll
            for (int np = 0; np < 2; np++) {
                int row = warpN + np * 16 + b_row_lo;
                uint32_t addr = bbase + ((uint32_t)((row << 3) + (cb ^ (row & 7))) << 4);
                ldsm4(bq[np], addr);
            }
#pragma unroll
            for (int mi = 0; mi < 4; mi++)
#pragma unroll
                for (int ni = 0; ni < 4; ni++)
                    mma_f16(acc[mi][ni], af[mi], &bq[ni >> 1][(ni & 1) * 2]);
        }
    }

#pragma unroll
    for (int mi = 0; mi < 4; mi++) {
        int row = row0 + warpM + mi * 16 + r;
#pragma unroll
        for (int ni = 0; ni < 4; ni++) {
            int col = col0 + warpN + ni * 8 + 2 * c;
            float o0 = alpha * acc[mi][ni][0], o1 = alpha * acc[mi][ni][1];
            float o2 = alpha * acc[mi][ni][2], o3 = alpha * acc[mi][ni][3];
            if (OUT_HALF) {
                __half* Ch = (__half*)Cv;
                *(__half2*)&Ch[(size_t)row * NC + col]       = __floats2half2_rn(o0, o1);
                *(__half2*)&Ch[(size_t)(row + 8) * NC + col] = __floats2half2_rn(o2, o3);
            } else {
                float* Cf = (float*)Cv;
                *(float2*)&Cf[(size_t)row * NC + col]       = make_float2(o0, o1);
                *(float2*)&Cf[(size_t)(row + 8) * NC + col] = make_float2(o2, o3);
            }
        }
    }
}

__global__ void __launch_bounds__(256, 2) qkv_h_kernel()
{
    if (blockIdx.z == 0)      gemm_fp16<true>(g_Xh, g_Wqh, g_Qh, D_MOD, D_MOD, 1.0f);
    else if (blockIdx.z == 1) gemm_fp16<true>(g_Xh, g_Wkh, g_Kh, D_MOD, D_MOD, 1.0f);
    else                      gemm_fp16<true>(g_Xh, g_Wvh, g_Vh, D_MOD, D_MOD, 1.0f);
}

__global__ void __launch_bounds__(256, 2) s_h_kernel(float* __restrict__ S)
{
    gemm_fp16<false>(g_Qh, g_Kh, S, D_MOD, N_TOK, 0.044194173824159216f); // 1/sqrt(512)
}

__global__ void __launch_bounds__(256, 2) z_h_kernel(float* __restrict__ Z)
{
    gemm_fp16<false>(g_Sh, g_Vth, Z, N_TOK, D_MOD, 1.0f);
}

// ---------------------------------------------------------------------------
// fused fp32 -> fp16 convert for x, Wq, Wk, Wv (one launch)
// ---------------------------------------------------------------------------
#define X4   (N_TOK * D_MOD / 4)
#define W4   (D_MOD * D_MOD / 4)

__global__ void cvt_all_kernel(const float4* __restrict__ x,
                               const float4* __restrict__ Wq,
                               const float4* __restrict__ Wk,
                               const float4* __restrict__ Wv)
{
    int i = blockIdx.x * blockDim.x + threadIdx.x;
    const float4* in;
    __half* out;
    int idx;
    if (i < X4)                { in = x;  out = g_Xh;  idx = i; }
    else if (i < X4 + W4)      { in = Wq; out = g_Wqh; idx = i - X4; }
    else if (i < X4 + 2 * W4)  { in = Wk; out = g_Wkh; idx = i - X4 - W4; }
    else if (i < X4 + 3 * W4)  { in = Wv; out = g_Wvh; idx = i - X4 - 2 * W4; }
    else return;
    float4 v = in[idx];
    *(__half2*)&out[idx * 4]     = __floats2half2_rn(v.x, v.y);
    *(__half2*)&out[idx * 4 + 2] = __floats2half2_rn(v.z, v.w);
}

// ---------------------------------------------------------------------------
// transpose g_Vh [4096][512] -> g_Vth [512][4096]
// ---------------------------------------------------------------------------
__global__ void transpose_v_kernel()
{
    __shared__ __half tile[32][33];
    const int c0 = blockIdx.x * 32;
    const int r0 = blockIdx.y * 32;
    const int tx = threadIdx.x & 31;
    const int ty = threadIdx.x >> 5;
#pragma unroll
    for (int i = 0; i < 4; i++) {
        int row = ty + i * 8;
        tile[row][tx] = g_Vh[(size_t)(r0 + row) * D_MOD + c0 + tx];
    }
    __syncthreads();
#pragma unroll
    for (int i = 0; i < 4; i++) {
        int row = ty + i * 8;
        g_Vth[(size_t)(c0 + row) * N_TOK + r0 + tx] = tile[tx][row];
    }
}

// ---------------------------------------------------------------------------
// sigma[i] = clip(x[i,:].Ws, 0.001, 1.0) — one warp per row (fp32 inputs)
// ---------------------------------------------------------------------------
__global__ void sigma_kernel(const float* __restrict__ x, const float* __restrict__ Ws)
{
    int row  = blockIdx.x * (blockDim.x >> 5) + (threadIdx.x >> 5);
    int lane = threadIdx.x & 31;
    if (row >= N_TOK) return;
    const float4* xr = (const float4*)(x + (size_t)row * D_MOD);
    const float4* w  = (const float4*)Ws;
    float s = 0.f;
#pragma unroll
    for (int k = lane; k < D_MOD / 4; k += 32) {
        float4 a = xr[k], b = w[k];
        s += a.x * b.x + a.y * b.y + a.z * b.z + a.w * b.w;
    }
#pragma unroll
    for (int o = 16; o; o >>= 1) s += __shfl_xor_sync(0xffffffffu, s, o);
    if (lane == 0) g_sigma[row] = fminf(fmaxf(s, 0.001f), 1.0f);
}

// ---------------------------------------------------------------------------
// P row kernel: zero the row, then Gaussian band (fp32 underflow makes the
// exp term exactly 0 for |i-j| >= 15 since sigma <= 1). One block per row.
// ---------------------------------------------------------------------------
#define BAND 32

__global__ void p_row_kernel(float* __restrict__ P)
{
    const int row = blockIdx.x;
    const int t = threadIdx.x;
    float4* prow4 = (float4*)(P + (size_t)row * N_TOK);
#pragma unroll
    for (int j = t; j < N_TOK / 4; j += 256)
        prow4[j] = make_float4(0.f, 0.f, 0.f, 0.f);
    __syncthreads();

    if (t < 32) {
        const int lane = t;
        const float sg  = g_sigma[row];
        const float inv = 1.0f / sg;
        const float cc  = rsqrtf(6.283185307179586f * sg);
        const int j0 = max(row - BAND, 0);
        const int j1 = min(row + BAND, N_TOK - 1);

        float sum = 0.f;
        for (int j = j0 + lane; j <= j1; j += 32) {
            float u = (float)(j - row) * inv;
            sum += cc * __expf(-0.5f * u * u);
        }
#pragma unroll
        for (int o = 16; o; o >>= 1) sum += __shfl_xor_sync(0xffffffffu, sum, o);
        const float scale = 1.0f / (sum + 1e-8f);

        for (int j = j0 + lane; j <= j1; j += 32) {
            float u = (float)(j - row) * inv;
            P[(size_t)row * N_TOK + j] = cc * __expf(-0.5f * u * u) * scale;
        }
    }
}

// ---------------------------------------------------------------------------
// in-place row softmax (no max pass: scores are far from fp32 overflow),
// also writes fp16 copy. One block per row.
// ---------------------------------------------------------------------------
__global__ void softmax_kernel(float* __restrict__ S, __half* __restrict__ Sh)
{
    __shared__ float buf[N_TOK];
    __shared__ float red[8];
    const int row = blockIdx.x;
    const int t = threadIdx.x;
    const int lane = t & 31, w = t >> 5;
    float*  srow  = S  + (size_t)row * N_TOK;
    __half* srowh = Sh + (size_t)row * N_TOK;

    float sum = 0.f;
    for (int j = t; j < N_TOK; j += 256) {
        float e = __expf(srow[j]);
        buf[j] = e;
        sum += e;
    }
#pragma unroll
    for (int o = 16; o; o >>= 1) sum += __shfl_xor_sync(0xffffffffu, sum, o);
    if (lane == 0) red[w] = sum;
    __syncthreads();
    if (t == 0) {
        float s = 0.f;
#pragma unroll
        for (int i = 0; i < 8; i++) s += red[i];
        red[0] = s;
    }
    __syncthreads();
    const float scale = 1.0f / red[0];

    for (int j = t; j < N_TOK; j += 256) {
        float v = buf[j] * scale;
        srow[j]  = v;
        srowh[j] = __float2half_rn(v);
    }
}

// ---------------------------------------------------------------------------
extern "C" void kernel_launch(void* const* d_in, const int* in_sizes, int n_in,
                              void* d_out, int out_size)
{
    const float* x  = (const float*)d_in[0];
    const float* Wq = (const float*)d_in[1];
    const float* Wk = (const float*)d_in[2];
    const float* Wv = (const float*)d_in[3];
    const float* Ws = (const float*)d_in[4];

    float* out = (float*)d_out;
    float* Z = out;                          // [4096, 512]
    float* P = out + (size_t)N_TOK * D_MOD;  // [4096, 4096]
    float* S = P + (size_t)N_TOK * N_TOK;    // [4096, 4096]

    cudaFuncSetAttribute(qkv_h_kernel, cudaFuncAttributeMaxDynamicSharedMemorySize, DYN_SMEM);
    cudaFuncSetAttribute(s_h_kernel,   cudaFuncAttributeMaxDynamicSharedMemorySize, DYN_SMEM);
    cudaFuncSetAttribute(z_h_kernel,   cudaFuncAttributeMaxDynamicSharedMemorySize, DYN_SMEM);

    __half* shp;
    cudaGetSymbolAddress((void**)&shp, g_Sh);

    dim3 blk(256);

    // 0) convert inputs to fp16 (one fused launch)
    cvt_all_kernel<<<(X4 + 3 * W4 + 255) / 256, blk>>>(
        (const float4*)x, (const float4*)Wq, (const float4*)Wk, (const float4*)Wv);

    // 1) Q, K, V = x @ W^T  (fp16 outputs)
    dim3 gQKV(D_MOD / 128, N_TOK / 128, 3);
    qkv_h_kernel<<<gQKV, blk, DYN_SMEM>>>();

    // 1b) Vt
    transpose_v_kernel<<<dim3(D_MOD / 32, N_TOK / 32), blk>>>();

    // 2) sigma
    sigma_kernel<<<N_TOK / 8, blk>>>(x, Ws);

    // 3) P = zeros + Gaussian band
    p_row_kernel<<<N_TOK, blk>>>(P);

    // 4) raw scores: S = (Q K^T)/sqrt(d)
    dim3 gS(N_TOK / 128, N_TOK / 128);
    s_h_kernel<<<gS, blk, DYN_SMEM>>>(S);

    // 5) softmax rows in place (+ fp16 copy)
    softmax_kernel<<<N_TOK, blk>>>(S, shp);

    // 6) Z = S @ V
    dim3 gZ(D_MOD / 128, N_TOK / 128);
    z_h_kernel<<<gZ, blk, DYN_SMEM>>>(Z);
}

// round 9
// speedup vs baseline: 1.4408x; 1.0636x over previous
#include <cuda_runtime.h>
#include <cuda_fp16.h>
#include <math.h>
#include <stdint.h>

#define N_TOK 4096
#define D_MOD 512

// scratch (static device globals — no allocation allowed)
__device__ __half g_Xh[N_TOK * D_MOD];
__device__ __half g_Wqh[D_MOD * D_MOD];
__device__ __half g_Wkh[D_MOD * D_MOD];
__device__ __half g_Wvh[D_MOD * D_MOD];
__device__ __half g_Qh[N_TOK * D_MOD];
__device__ __half g_Kh[N_TOK * D_MOD];
__device__ __half g_Vh[N_TOK * D_MOD];
__device__ __half g_Vth[D_MOD * N_TOK];      // V^T [512][4096]
__device__ __half g_Sh[(size_t)N_TOK * N_TOK];  // exp(scores), unnormalized
__device__ float  g_sigma[N_TOK];            // accumulated x.Ws (clamp at use)
__device__ float  g_rowsum[N_TOK];           // sum of exp per row

__device__ __forceinline__ uint32_t smem_u32(const void* p) {
    uint32_t a;
    asm("{ .reg .u64 t; cvta.to.shared.u64 t, %1; cvt.u32.u64 %0, t; }" : "=r"(a) : "l"(p));
    return a;
}
__device__ __forceinline__ void mma_f16(float* d, const uint32_t* a, const uint32_t* b) {
    asm volatile(
        "mma.sync.aligned.m16n8k16.row.col.f32.f16.f16.f32 "
        "{%0,%1,%2,%3}, {%4,%5,%6,%7}, {%8,%9}, {%0,%1,%2,%3};"
        : "+f"(d[0]), "+f"(d[1]), "+f"(d[2]), "+f"(d[3])
        : "r"(a[0]), "r"(a[1]), "r"(a[2]), "r"(a[3]), "r"(b[0]), "r"(b[1]));
}
__device__ __forceinline__ void ldsm4(uint32_t* r, uint32_t addr) {
    asm volatile("ldmatrix.sync.aligned.m8n8.x4.shared.b16 {%0,%1,%2,%3}, [%4];"
        : "=r"(r[0]), "=r"(r[1]), "=r"(r[2]), "=r"(r[3]) : "r"(addr));
}
__device__ __forceinline__ void cp16(uint32_t s, const void* g) {
    asm volatile("cp.async.cg.shared.global [%0], [%1], 16;" :: "r"(s), "l"(g));
}

// ---------------------------------------------------------------------------
// cp.async 3-stage fp16 GEMM (fp32 accumulate), ldmatrix fragment loads.
//   C[M,NC] = alpha * A[M,K] * B[NC,K]^T   (both K-major row-major fp16)
// Epilogue modes:
//   0: fp32 store
//   1: fp16 store (qkv)
//   2: e = exp(alpha*acc) -> fp16 store + per-row sum atomics (S kernel)
//   3: fp32 store scaled by 1/g_rowsum[row]  (Z kernel)
// 96 KB smem -> 2 CTAs/SM.
// ---------------------------------------------------------------------------
#define STAGES 3
#define TILE_BYTES 16384
#define STAGE_BYTES (2 * TILE_BYTES)
#define DYN_SMEM (STAGES * STAGE_BYTES)       // 96 KB

template <int MODE>
__device__ __forceinline__ void gemm_fp16(
    const __half* __restrict__ A, const __half* __restrict__ B,
    void* __restrict__ Cv, int K, int NC, float alpha)
{
    extern __shared__ __half smh[];
    const uint32_t smem_base = smem_u32(smh);
    const int t    = threadIdx.x;
    const int wid  = t >> 5;
    const int lane = t & 31;
    const int r    = lane >> 2;
    const int c    = lane & 3;
    const int warpM = (wid >> 2) * 64;
    const int warpN = (wid & 3) * 32;
    const int row0 = blockIdx.y * 128;
    const int col0 = blockIdx.x * 128;
    const int iters = K >> 6;

    auto stage_load = [&](int sidx) {
        const int buf = sidx % STAGES;
        const int k0  = sidx << 6;
        const uint32_t abase = smem_base + (uint32_t)buf * STAGE_BYTES;
        const uint32_t bbase = abase + TILE_BYTES;
#pragma unroll
        for (int i = 0; i < 4; i++) {
            int lc = i * 256 + t;
            int rr = lc >> 3, cc = lc & 7;
            uint32_t so = (uint32_t)((rr << 3) + (cc ^ (rr & 7))) << 4;
            cp16(abase + so, &A[(size_t)(row0 + rr) * K + k0 + (cc << 3)]);
            cp16(bbase + so, &B[(size_t)(col0 + rr) * K + k0 + (cc << 3)]);
        }
        asm volatile("cp.async.commit_group;" ::: "memory");
    };

    const int a_row_lo = lane & 15;
    const int a_chi    = lane >> 4;
    const int b_row_lo = (lane & 7) + ((lane >> 4) << 3);
    const int b_chi    = (lane >> 3) & 1;

    float acc[4][4][4] = {};

    stage_load(0);
    stage_load(1);

    for (int it = 0; it < iters; ++it) {
        const int buf = it % STAGES;
        asm volatile("cp.async.wait_group %0;" :: "n"(STAGES - 2) : "memory");
        __syncthreads();
        if (it + STAGES - 1 < iters) stage_load(it + STAGES - 1);

        const uint32_t abase = smem_base + (uint32_t)buf * STAGE_BYTES;
        const uint32_t bbase = abase + TILE_BYTES;

#pragma unroll
        for (int kk4 = 0; kk4 < 4; kk4++) {
            const int ca = kk4 * 2 + a_chi;
            const int cb = kk4 * 2 + b_chi;
            uint32_t af[4][4], bq[2][4];
#pragma unroll
            for (int mi = 0; mi < 4; mi++) {
                int row = warpM + mi * 16 + a_row_lo;
                uint32_t addr = abase + ((uint32_t)((row << 3) + (ca ^ (row & 7))) << 4);
                ldsm4(af[mi], addr);
            }
#pragma unroll
            for (int np = 0; np < 2; np++) {
                int row = warpN + np * 16 + b_row_lo;
                uint32_t addr = bbase + ((uint32_t)((row << 3) + (cb ^ (row & 7))) << 4);
                ldsm4(bq[np], addr);
            }
#pragma unroll
            for (int mi = 0; mi < 4; mi++)
#pragma unroll
                for (int ni = 0; ni < 4; ni++)
                    mma_f16(acc[mi][ni], af[mi], &bq[ni >> 1][(ni & 1) * 2]);
        }
    }

    // ---- epilogue
#pragma unroll
    for (int mi = 0; mi < 4; mi++) {
        int row = row0 + warpM + mi * 16 + r;
        float rs0 = 0.f, rs1 = 0.f;
        float inv0 = 1.f, inv1 = 1.f;
        if (MODE == 3) {
            inv0 = 1.0f / g_rowsum[row];
            inv1 = 1.0f / g_rowsum[row + 8];
        }
#pragma unroll
        for (int ni = 0; ni < 4; ni++) {
            int col = col0 + warpN + ni * 8 + 2 * c;
            float o0 = alpha * acc[mi][ni][0], o1 = alpha * acc[mi][ni][1];
            float o2 = alpha * acc[mi][ni][2], o3 = alpha * acc[mi][ni][3];
            if (MODE == 1) {
                __half* Ch = (__half*)Cv;
                *(__half2*)&Ch[(size_t)row * NC + col]       = __floats2half2_rn(o0, o1);
                *(__half2*)&Ch[(size_t)(row + 8) * NC + col] = __floats2half2_rn(o2, o3);
            } else if (MODE == 2) {
                float e0 = fminf(__expf(o0), 60000.f);
                float e1 = fminf(__expf(o1), 60000.f);
                float e2 = fminf(__expf(o2), 60000.f);
                float e3 = fminf(__expf(o3), 60000.f);
                __half* Ch = (__half*)Cv;
                *(__half2*)&Ch[(size_t)row * NC + col]       = __floats2half2_rn(e0, e1);
                *(__half2*)&Ch[(size_t)(row + 8) * NC + col] = __floats2half2_rn(e2, e3);
                rs0 += e0 + e1;
                rs1 += e2 + e3;
            } else if (MODE == 3) {
                float* Cf = (float*)Cv;
                *(float2*)&Cf[(size_t)row * NC + col]       = make_float2(o0 * inv0, o1 * inv0);
                *(float2*)&Cf[(size_t)(row + 8) * NC + col] = make_float2(o2 * inv1, o3 * inv1);
            } else {
                float* Cf = (float*)Cv;
                *(float2*)&Cf[(size_t)row * NC + col]       = make_float2(o0, o1);
                *(float2*)&Cf[(size_t)(row + 8) * NC + col] = make_float2(o2, o3);
            }
        }
        if (MODE == 2) {
            rs0 += __shfl_xor_sync(0xffffffffu, rs0, 1);
            rs0 += __shfl_xor_sync(0xffffffffu, rs0, 2);
            rs1 += __shfl_xor_sync(0xffffffffu, rs1, 1);
            rs1 += __shfl_xor_sync(0xffffffffu, rs1, 2);
            if (c == 0) {
                atomicAdd(&g_rowsum[row],     rs0);
                atomicAdd(&g_rowsum[row + 8], rs1);
            }
        }
    }
}

__global__ void __launch_bounds__(256, 2) qkv_h_kernel()
{
    if (blockIdx.z == 0)      gemm_fp16<1>(g_Xh, g_Wqh, g_Qh, D_MOD, D_MOD, 1.0f);
    else if (blockIdx.z == 1) gemm_fp16<1>(g_Xh, g_Wkh, g_Kh, D_MOD, D_MOD, 1.0f);
    else                      gemm_fp16<1>(g_Xh, g_Wvh, g_Vh, D_MOD, D_MOD, 1.0f);
}

__global__ void __launch_bounds__(256, 2) s_h_kernel()
{
    // exp((Q K^T)/sqrt(d)) -> g_Sh + row sums
    gemm_fp16<2>(g_Qh, g_Kh, g_Sh, D_MOD, N_TOK, 0.044194173824159216f);
}

__global__ void __launch_bounds__(256, 2) z_h_kernel(float* __restrict__ Z)
{
    // Z = diag(1/rowsum) * E * V
    gemm_fp16<3>(g_Sh, g_Vth, Z, N_TOK, D_MOD, 1.0f);
}

// ---------------------------------------------------------------------------
// fused fp32 -> fp16 convert for x, Wq, Wk, Wv + sigma partial dot (x rows)
// ---------------------------------------------------------------------------
#define X4   (N_TOK * D_MOD / 4)
#define W4   (D_MOD * D_MOD / 4)

__global__ void cvt_all_kernel(const float4* __restrict__ x,
                               const float4* __restrict__ Wq,
                               const float4* __restrict__ Wk,
                               const float4* __restrict__ Wv,
                               const float4* __restrict__ Ws)
{
    int i = blockIdx.x * blockDim.x + threadIdx.x;
    if (i < X4) {
        float4 v = x[i];
        *(__half2*)&g_Xh[i * 4]     = __floats2half2_rn(v.x, v.y);
        *(__half2*)&g_Xh[i * 4 + 2] = __floats2half2_rn(v.z, v.w);
        // sigma partial: warp covers 128 consecutive floats of one row
        float4 w = Ws[i & 127];
        float s = v.x * w.x + v.y * w.y + v.z * w.z + v.w * w.w;
#pragma unroll
        for (int o = 16; o; o >>= 1) s += __shfl_xor_sync(0xffffffffu, s, o);
        if ((threadIdx.x & 31) == 0) atomicAdd(&g_sigma[i >> 7], s);
        return;
    }
    const float4* in;
    __half* out;
    int idx;
    if (i < X4 + W4)           { in = Wq; out = g_Wqh; idx = i - X4; }
    else if (i < X4 + 2 * W4)  { in = Wk; out = g_Wkh; idx = i - X4 - W4; }
    else if (i < X4 + 3 * W4)  { in = Wv; out = g_Wvh; idx = i - X4 - 2 * W4; }
    else return;
    float4 v = in[idx];
    *(__half2*)&out[idx * 4]     = __floats2half2_rn(v.x, v.y);
    *(__half2*)&out[idx * 4 + 2] = __floats2half2_rn(v.z, v.w);
}

// ---------------------------------------------------------------------------
// transpose g_Vh [4096][512] -> g_Vth [512][4096]
// ---------------------------------------------------------------------------
__global__ void transpose_v_kernel()
{
    __shared__ __half tile[32][33];
    const int c0 = blockIdx.x * 32;
    const int r0 = blockIdx.y * 32;
    const int tx = threadIdx.x & 31;
    const int ty = threadIdx.x >> 5;
#pragma unroll
    for (int i = 0; i < 4; i++) {
        int row = ty + i * 8;
        tile[row][tx] = g_Vh[(size_t)(r0 + row) * D_MOD + c0 + tx];
    }
    __syncthreads();
#pragma unroll
    for (int i = 0; i < 4; i++) {
        int row = ty + i * 8;
        g_Vth[(size_t)(c0 + row) * N_TOK + r0 + tx] = tile[tx][row];
    }
}

// ---------------------------------------------------------------------------
// P row kernel: zero row + Gaussian band; clamps sigma at use.
// fp32 underflow: exp term is exactly 0 for |i-j| >= 15 since sigma <= 1.
// ---------------------------------------------------------------------------
#define BAND 32

__global__ void p_row_kernel(float* __restrict__ P)
{
    const int row = blockIdx.x;
    const int t = threadIdx.x;
    float4* prow4 = (float4*)(P + (size_t)row * N_TOK);
#pragma unroll
    for (int j = t; j < N_TOK / 4; j += 256)
        prow4[j] = make_float4(0.f, 0.f, 0.f, 0.f);
    __syncthreads();

    if (t < 32) {
        const int lane = t;
        const float sg  = fminf(fmaxf(g_sigma[row], 0.001f), 1.0f);
        const float inv = 1.0f / sg;
        const float cc  = rsqrtf(6.283185307179586f * sg);
        const int j0 = max(row - BAND, 0);
        const int j1 = min(row + BAND, N_TOK - 1);

        float sum = 0.f;
        for (int j = j0 + lane; j <= j1; j += 32) {
            float u = (float)(j - row) * inv;
            sum += cc * __expf(-0.5f * u * u);
        }
#pragma unroll
        for (int o = 16; o; o >>= 1) sum += __shfl_xor_sync(0xffffffffu, sum, o);
        const float scale = 1.0f / (sum + 1e-8f);

        for (int j = j0 + lane; j <= j1; j += 32) {
            float u = (float)(j - row) * inv;
            P[(size_t)row * N_TOK + j] = cc * __expf(-0.5f * u * u) * scale;
        }
    }
}

// ---------------------------------------------------------------------------
// scale S: S_fp32 = e_fp16 * (1/rowsum). 4 blocks per row, 4 floats/thread.
// ---------------------------------------------------------------------------
__global__ void scale_s_kernel(float* __restrict__ S)
{
    __shared__ float sh_inv;
    const int b = blockIdx.x;          // 16384 blocks
    const int row = b >> 2;
    if (threadIdx.x == 0) sh_inv = 1.0f / g_rowsum[row];
    __syncthreads();
    const float inv = sh_inv;
    const size_t base = (size_t)b * 1024 + threadIdx.x * 4;
    __half2 h01 = *(const __half2*)&g_Sh[base];
    __half2 h23 = *(const __half2*)&g_Sh[base + 2];
    float2 f01 = __half22float2(h01);
    float2 f23 = __half22float2(h23);
    float4 o;
    o.x = f01.x * inv; o.y = f01.y * inv;
    o.z = f23.x * inv; o.w = f23.y * inv;
    *(float4*)&S[base] = o;
}

// ---------------------------------------------------------------------------
extern "C" void kernel_launch(void* const* d_in, const int* in_sizes, int n_in,
                              void* d_out, int out_size)
{
    const float* x  = (const float*)d_in[0];
    const float* Wq = (const float*)d_in[1];
    const float* Wk = (const float*)d_in[2];
    const float* Wv = (const float*)d_in[3];
    const float* Ws = (const float*)d_in[4];

    float* out = (float*)d_out;
    float* Z = out;                          // [4096, 512]
    float* P = out + (size_t)N_TOK * D_MOD;  // [4096, 4096]
    float* S = P + (size_t)N_TOK * N_TOK;    // [4096, 4096]

    cudaFuncSetAttribute(qkv_h_kernel, cudaFuncAttributeMaxDynamicSharedMemorySize, DYN_SMEM);
    cudaFuncSetAttribute(s_h_kernel,   cudaFuncAttributeMaxDynamicSharedMemorySize, DYN_SMEM);
    cudaFuncSetAttribute(z_h_kernel,   cudaFuncAttributeMaxDynamicSharedMemorySize, DYN_SMEM);

    float *sigp, *rsp;
    cudaGetSymbolAddress((void**)&sigp, g_sigma);
    cudaGetSymbolAddress((void**)&rsp,  g_rowsum);

    dim3 blk(256);

    // 0) zero accumulators
    cudaMemsetAsync(sigp, 0, N_TOK * sizeof(float));
    cudaMemsetAsync(rsp,  0, N_TOK * sizeof(float));

    // 1) convert inputs to fp16 + sigma partial sums (one launch)
    cvt_all_kernel<<<(X4 + 3 * W4) / 256, blk>>>(
        (const float4*)x, (const float4*)Wq, (const float4*)Wk,
        (const float4*)Wv, (const float4*)Ws);

    // 2) Q, K, V = x @ W^T  (fp16 outputs)
    dim3 gQKV(D_MOD / 128, N_TOK / 128, 3);
    qkv_h_kernel<<<gQKV, blk, DYN_SMEM>>>();

    // 2b) Vt
    transpose_v_kernel<<<dim3(D_MOD / 32, N_TOK / 32), blk>>>();

    // 3) P = zeros + Gaussian band (sigma clamped at use)
    p_row_kernel<<<N_TOK, blk>>>(P);

    // 4) E = exp((Q K^T)/sqrt(d)) -> g_Sh (fp16) + row sums
    dim3 gS(N_TOK / 128, N_TOK / 128);
    s_h_kernel<<<gS, blk, DYN_SMEM>>>();

    // 5) S output = E / rowsum
    scale_s_kernel<<<N_TOK * 4, blk>>>(S);

    // 6) Z = diag(1/rowsum) E V
    dim3 gZ(D_MOD / 128, N_TOK / 128);
    z_h_kernel<<<gZ, blk, DYN_SMEM>>>(Z);
}